// round 15
// baseline (speedup 1.0000x reference)
#include <cuda_runtime.h>

#define EE 25
#define HH 37
#define NJ 6
#define ROW15 15                // f2 per halfplane row
#define HPF2 585                // 39 rows * 15 f2 per halfplane
#define HE0 0                   // plane0 even cols
#define HO0 585                 // plane0 odd cols
#define HE1 1170
#define HO1 1755
#define HE2 2340
#define HO2 2925
#define NF2 3510                // f2 per buffer (6 halfplanes)
#define NTH 320
#define GAMMA 0.9f
#define ADDC 12

// dr = {0,1,1,0,-1,-1} ; dc = {1,0,-1,-1,0,1}  packed (d+1), 2 bits per k
#define DR_PACK 105u
#define DC_PACK 2310u

#define SMEM_BYTES (2 * NF2 * 8)   // 56160 B -> 4 CTAs/SM

__device__ __forceinline__ float bf(unsigned m, int k) {
    return ((m >> k) & 1u) ? 1.0f : 0.0f;
}

__global__ __launch_bounds__(NTH, 4) void vin_kernel(
    const float* __restrict__ goals,   // [B,6,25,25]
    const int*   __restrict__ state,   // [B,3]
    const float* __restrict__ obst,    // [B,25,25]
    const int*   __restrict__ n_iter,  // [1]
    float* __restrict__ out)           // [B,4]
{
    extern __shared__ float2 smf2[];

    const int b   = blockIdx.x;
    const int tid = threadIdx.x;

    // ---- zero both buffers (7020 f2 = 3510 float4) ----
    {
        float4* z4 = (float4*)smf2;
        for (int i = tid; i < NF2; i += NTH)
            z4[i] = make_float4(0.f, 0.f, 0.f, 0.f);
    }
    __syncthreads();

    const int band = tid >> 4;
    const int q    = tid & 15;
    const bool active = (q < 13) && (band < 19);

    int t0 = 0, t1 = 0;
    float AmP = 0.f, AmQ = 0.f, AmR = 0.f, AmS = 0.f;
    unsigned cgq = 0u;   // P: bits 0-5, Q: 6-11, R: 12-17, S: 18-23
    float2 oP0, oP1, oP2, oQ0, oQ1, oQ2, oR0, oR1, oR2, oS0, oS1, oS2;
    oP0 = oP1 = oP2 = oQ0 = oQ1 = oQ2 = make_float2(0.f, 0.f);
    oR0 = oR1 = oR2 = oS0 = oS1 = oS2 = make_float2(0.f, 0.f);

    if (active) {
        int rA = 2 * band, rB = rA + 1;
        int cL = 2 * q,    cR = cL + 1;
        int rowA  = rA + 1;                            // prow of rA
        int rowBp = (band == 18) ? 38 : (rowA + 2);    // prow of rB+1 (clamped; band18 row dead)
        t0 = rowA  * ROW15 + q;
        t1 = rowBp * ROW15 + q;

        // per-cell masks straight from global
        int rr[2] = { rA, rB };
        int cc[2] = { cL, cR };
        float Amv[4];
        #pragma unroll
        for (int ri = 0; ri < 2; ++ri) {
            #pragma unroll
            for (int ci = 0; ci < 2; ++ci) {
                int cell = ri * 2 + ci;          // 0=P 1=Q 2=R 3=S
                int r = rr[ri], c = cc[ci];
                float Am = 0.f;
                unsigned g = 0u;
                if (r < HH && c < EE) {
                    int u = r + (c >> 1) - ADDC;
                    if (u >= 0 && u < EE) {
                        if (obst[(b * EE + u) * EE + c] == 0.0f) {
                            Am = GAMMA;
                            #pragma unroll
                            for (int j = 0; j < NJ; ++j)
                                if (goals[((b * NJ + j) * EE + u) * EE + c] != 0.0f)
                                    g |= (1u << j);
                        }
                    }
                }
                Amv[cell] = Am;
                int shift = (cell == 0) ? 0 : (cell == 1) ? 6 : (cell == 2) ? 12 : 18;
                cgq |= g << shift;
            }
        }
        AmP = Amv[0]; AmQ = Amv[1]; AmR = Amv[2]; AmS = Amv[3];

        // seed o = goal indicators (s_plus with val = 0)
        oP0 = make_float2(bf(cgq, 0),  bf(cgq, 3));
        oP1 = make_float2(bf(cgq, 1),  bf(cgq, 4));
        oP2 = make_float2(bf(cgq, 2),  bf(cgq, 5));
        oQ0 = make_float2(bf(cgq, 6),  bf(cgq, 9));
        oQ1 = make_float2(bf(cgq, 7),  bf(cgq, 10));
        oQ2 = make_float2(bf(cgq, 8),  bf(cgq, 11));
        oR0 = make_float2(bf(cgq, 12), bf(cgq, 15));
        oR1 = make_float2(bf(cgq, 13), bf(cgq, 16));
        oR2 = make_float2(bf(cgq, 14), bf(cgq, 17));
        oS0 = make_float2(bf(cgq, 18), bf(cgq, 21));
        oS1 = make_float2(bf(cgq, 19), bf(cgq, 22));
        oS2 = make_float2(bf(cgq, 20), bf(cgq, 23));

        float2* Db = smf2;   // buffer A
        Db[HE0 + t0 + 1]  = oP0;  Db[HO0 + t0 + 1]  = oQ0;
        Db[HE0 + t0 + 16] = oR0;  Db[HO0 + t0 + 16] = oS0;
        Db[HE1 + t0 + 1]  = oP1;  Db[HO1 + t0 + 1]  = oQ1;
        Db[HE1 + t0 + 16] = oR1;  Db[HO1 + t0 + 16] = oS1;
        Db[HE2 + t0 + 1]  = oP2;  Db[HO2 + t0 + 1]  = oQ2;
        Db[HE2 + t0 + 16] = oR2;  Db[HO2 + t0 + 16] = oS2;
    }
    __syncthreads();

    const int iters = n_iter[0];
    int spO2 = 0;

    for (int s = 0; s < iters; ++s) {
        if (active) {
            const float2* S = smf2 + spO2;
            float2*       D = smf2 + (spO2 ^ NF2);

            // 14 f2 loads, all 8B lane stride (2-wavefront floor each)
            float2 A  = S[HO0 + t0];        // P0 (rA, cL-1)
            float2 Bx = S[HO0 + t0 + 15];   // P0 (rB, cL-1)
            float2 C  = S[HE0 + t0 + 2];    // P0 (rA, cR+1)
            float2 Dx = S[HE0 + t0 + 17];   // P0 (rB, cR+1)
            float2 UL = S[HE1 + t0 - 14];   // P1 (rA-1, cL)
            float2 UR = S[HO1 + t0 - 14];   // P1 (rA-1, cR)
            float2 NL = S[HE1 + t1 + 1];    // P1 (rB+1, cL)
            float2 NR = S[HO1 + t1 + 1];    // P1 (rB+1, cR)
            float2 E_ = S[HO2 + t0 + 15];   // P2 (rB,   cL-1)
            float2 F  = S[HO2 + t1];        // P2 (rB+1, cL-1)
            float2 G  = S[HE2 + t1 + 1];    // P2 (rB+1, cL)
            float2 Hh = S[HO2 + t0 - 14];   // P2 (rA-1, cR)
            float2 I  = S[HE2 + t0 - 13];   // P2 (rA-1, cR+1)
            float2 J  = S[HE2 + t0 + 2];    // P2 (rA,   cR+1)

            // P: n0=oQ0 n1=oR1 n2=E_ n3=A n4=UL n5=Hh
            float mP0 = fmaxf(fmaxf(oQ0.x, A.x),  fmaxf(oP1.x, oP2.y));
            float mP1 = fmaxf(fmaxf(oR1.x, UL.x), fmaxf(oP2.x, oP0.x));
            float mP2 = fmaxf(fmaxf(E_.x,  Hh.x), fmaxf(oP0.y, oP1.x));
            float mP3 = fmaxf(fmaxf(A.y,   oQ0.y), fmaxf(oP1.y, oP2.x));
            float mP4 = fmaxf(fmaxf(UL.y,  oR1.y), fmaxf(oP2.y, oP0.y));
            float mP5 = fmaxf(fmaxf(Hh.y,  E_.y), fmaxf(oP0.x, oP1.y));

            // Q: n0=C n1=oS1 n2=oR2 n3=oP0 n4=UR n5=I
            float mQ0 = fmaxf(fmaxf(C.x,   oP0.x), fmaxf(oQ1.x, oQ2.y));
            float mQ1 = fmaxf(fmaxf(oS1.x, UR.x), fmaxf(oQ2.x, oQ0.x));
            float mQ2 = fmaxf(fmaxf(oR2.x, I.x),  fmaxf(oQ0.y, oQ1.x));
            float mQ3 = fmaxf(fmaxf(oP0.y, C.y),  fmaxf(oQ1.y, oQ2.x));
            float mQ4 = fmaxf(fmaxf(UR.y,  oS1.y), fmaxf(oQ2.y, oQ0.y));
            float mQ5 = fmaxf(fmaxf(I.y,   oR2.y), fmaxf(oQ0.x, oQ1.y));

            // R: n0=oS0 n1=NL n2=F n3=Bx n4=oP1 n5=oQ2
            float mR0 = fmaxf(fmaxf(oS0.x, Bx.x), fmaxf(oR1.x, oR2.y));
            float mR1 = fmaxf(fmaxf(NL.x,  oP1.x), fmaxf(oR2.x, oR0.x));
            float mR2 = fmaxf(fmaxf(F.x,   oQ2.x), fmaxf(oR0.y, oR1.x));
            float mR3 = fmaxf(fmaxf(Bx.y,  oS0.y), fmaxf(oR1.y, oR2.x));
            float mR4 = fmaxf(fmaxf(oP1.y, NL.y), fmaxf(oR2.y, oR0.y));
            float mR5 = fmaxf(fmaxf(oQ2.y, F.y),  fmaxf(oR0.x, oR1.y));

            // S: n0=Dx n1=NR n2=G n3=oR0 n4=oQ1 n5=J
            float mS0 = fmaxf(fmaxf(Dx.x,  oR0.x), fmaxf(oS1.x, oS2.y));
            float mS1 = fmaxf(fmaxf(NR.x,  oQ1.x), fmaxf(oS2.x, oS0.x));
            float mS2 = fmaxf(fmaxf(G.x,   J.x),  fmaxf(oS0.y, oS1.x));
            float mS3 = fmaxf(fmaxf(oR0.y, Dx.y), fmaxf(oS1.y, oS2.x));
            float mS4 = fmaxf(fmaxf(oQ1.y, NR.y), fmaxf(oS2.y, oS0.y));
            float mS5 = fmaxf(fmaxf(J.y,   G.y),  fmaxf(oS0.x, oS1.y));

            oP0.x = fmaf(AmP, mP0, bf(cgq, 0));
            oP0.y = fmaf(AmP, mP3, bf(cgq, 3));
            oP1.x = fmaf(AmP, mP1, bf(cgq, 1));
            oP1.y = fmaf(AmP, mP4, bf(cgq, 4));
            oP2.x = fmaf(AmP, mP2, bf(cgq, 2));
            oP2.y = fmaf(AmP, mP5, bf(cgq, 5));
            oQ0.x = fmaf(AmQ, mQ0, bf(cgq, 6));
            oQ0.y = fmaf(AmQ, mQ3, bf(cgq, 9));
            oQ1.x = fmaf(AmQ, mQ1, bf(cgq, 7));
            oQ1.y = fmaf(AmQ, mQ4, bf(cgq, 10));
            oQ2.x = fmaf(AmQ, mQ2, bf(cgq, 8));
            oQ2.y = fmaf(AmQ, mQ5, bf(cgq, 11));
            oR0.x = fmaf(AmR, mR0, bf(cgq, 12));
            oR0.y = fmaf(AmR, mR3, bf(cgq, 15));
            oR1.x = fmaf(AmR, mR1, bf(cgq, 13));
            oR1.y = fmaf(AmR, mR4, bf(cgq, 16));
            oR2.x = fmaf(AmR, mR2, bf(cgq, 14));
            oR2.y = fmaf(AmR, mR5, bf(cgq, 17));
            oS0.x = fmaf(AmS, mS0, bf(cgq, 18));
            oS0.y = fmaf(AmS, mS3, bf(cgq, 21));
            oS1.x = fmaf(AmS, mS1, bf(cgq, 19));
            oS1.y = fmaf(AmS, mS4, bf(cgq, 22));
            oS2.x = fmaf(AmS, mS2, bf(cgq, 20));
            oS2.y = fmaf(AmS, mS5, bf(cgq, 23));

            D[HE0 + t0 + 1]  = oP0;  D[HO0 + t0 + 1]  = oQ0;
            D[HE0 + t0 + 16] = oR0;  D[HO0 + t0 + 16] = oS0;
            D[HE1 + t0 + 1]  = oP1;  D[HO1 + t0 + 1]  = oQ1;
            D[HE1 + t0 + 16] = oR1;  D[HO1 + t0 + 16] = oS1;
            D[HE2 + t0 + 1]  = oP2;  D[HO2 + t0 + 1]  = oQ2;
            D[HE2 + t0 + 16] = oR2;  D[HO2 + t0 + 16] = oS2;
        }
        spO2 ^= NF2;
        __syncthreads();
    }
    // final s_plus in buffer at offset spO2

    if (tid < 4) {
        int a     = tid;
        int alpha = state[b * 3 + 0];
        int u     = state[b * 3 + 1];
        int v     = state[b * 3 + 2];
        int rot   = (alpha + 1) % 6;
        int uu    = u - (v >> 1) + ADDC;

        int p, ddr = 0, ddc = 0;
        int drr = (int)((DR_PACK >> (2 * rot)) & 3u) - 1;
        int dcc = (int)((DC_PACK >> (2 * rot)) & 3u) - 1;
        if (a == 0)      { p = rot; ddr =  drr; ddc =  dcc; }
        else if (a == 1) { p = rot; ddr = -drr; ddc = -dcc; }
        else if (a == 2) { p = (rot + 1) % 6; }
        else             { p = (rot + 5) % 6; }

        float qv = 0.0f;
        if (obst[(b * EE + u) * EE + v] == 0.0f) {
            int pm  = p % 3;
            int col = v + ddc;                 // -1 .. 25
            int row = uu + ddr;                // -1 .. 37
            int par = col & 1;
            int k   = (col + 2) >> 1;
            float2 val = smf2[spO2 + (2 * pm + par) * HPF2 + (row + 1) * ROW15 + k];
            qv = (p < 3) ? val.x : val.y;
        }
        out[b * 4 + a] = qv;
    }
}

extern "C" void kernel_launch(void* const* d_in, const int* in_sizes, int n_in,
                              void* d_out, int out_size) {
    const float* goals  = (const float*)d_in[0];
    const int*   state  = (const int*)  d_in[1];
    const float* obst   = (const float*)d_in[2];
    const int*   n_iter = (const int*)  d_in[3];
    float* out = (float*)d_out;

    cudaFuncSetAttribute(vin_kernel,
                         cudaFuncAttributeMaxDynamicSharedMemorySize, SMEM_BYTES);

    int B = out_size / 4;   // 512
    vin_kernel<<<B, NTH, SMEM_BYTES>>>(goals, state, obst, n_iter, out);
}

// round 17
// speedup vs baseline: 1.4094x; 1.4094x over previous
#include <cuda_runtime.h>

#define EE 25
#define HH 37
#define NJ 6
#define PEC 30                  // padded cols (even), pc = c + 2
#define P0B 0                   // plane0: 38 rows (prow = r, 0..37)
#define P1B 1140                // plane1: 40 rows (prow = r+1, 0..39)
#define P2B 2340                // plane2: 40 rows (prow = r+1, 0..39)
#define NF2 3540                // f2 per buffer
#define NQ 13                   // quads per band
#define NBANDS 19
#define NQUAD (NQ * NBANDS)     // 247 quads
#define NTH 128
#define NU 2                    // quads per thread
#define GAMMA 0.9f
#define ADDC 12

// dr = {0,1,1,0,-1,-1} ; dc = {1,0,-1,-1,0,1}  packed (d+1), 2 bits per k
#define DR_PACK 105u
#define DC_PACK 2310u

#define SMEM_BYTES (2 * NF2 * 8)   // 56640 B -> 4 CTAs/SM

__device__ __forceinline__ float bf(unsigned m, int k) {
    return ((m >> k) & 1u) ? 1.0f : 0.0f;
}

__global__ __launch_bounds__(NTH, 4) void vin_kernel(
    const float* __restrict__ goals,   // [B,6,25,25]
    const int*   __restrict__ state,   // [B,3]
    const float* __restrict__ obst,    // [B,25,25]
    const int*   __restrict__ n_iter,  // [1]
    float* __restrict__ out)           // [B,4]
{
    extern __shared__ float2 smf2[];

    const int b   = blockIdx.x;
    const int tid = threadIdx.x;

    // ---- zero both buffers (7080 f2 = 3540 float4) ----
    {
        float4* z4 = (float4*)smf2;
        for (int i = tid; i < NF2; i += NTH)
            z4[i] = make_float4(0.f, 0.f, 0.f, 0.f);
    }
    __syncthreads();

    bool     act[NU];
    int      k0[NU], k1[NU], k2[NU];
    float    AmP[NU], AmQ[NU], AmR[NU], AmS[NU];
    unsigned cgq[NU];
    float2 oP0[NU], oP1[NU], oP2[NU], oQ0[NU], oQ1[NU], oQ2[NU];
    float2 oR0[NU], oR1[NU], oR2[NU], oS0[NU], oS1[NU], oS2[NU];

    #pragma unroll
    for (int u = 0; u < NU; ++u) {
        int qid = tid + u * NTH;
        act[u] = (qid < NQUAD);
        k0[u] = k1[u] = k2[u] = 0;
        AmP[u] = AmQ[u] = AmR[u] = AmS[u] = 0.f;
        cgq[u] = 0u;
        oP0[u] = oP1[u] = oP2[u] = make_float2(0.f, 0.f);
        oQ0[u] = oQ1[u] = oQ2[u] = make_float2(0.f, 0.f);
        oR0[u] = oR1[u] = oR2[u] = make_float2(0.f, 0.f);
        oS0[u] = oS1[u] = oS2[u] = make_float2(0.f, 0.f);

        if (act[u]) {
            int band = qid / NQ;
            int q    = qid - band * NQ;
            int rA = 2 * band, rB = rA + 1;
            int cL = 2 * q,    cR = cL + 1;
            k0[u] = P0B + rA * PEC + cL + 2;
            k1[u] = P1B + (rA + 1) * PEC + cL + 2;
            k2[u] = P2B + (rA + 1) * PEC + cL + 2;

            int rr[2] = { rA, rB };
            int cc[2] = { cL, cR };
            float Amv[4];
            #pragma unroll
            for (int ri = 0; ri < 2; ++ri) {
                #pragma unroll
                for (int ci = 0; ci < 2; ++ci) {
                    int cell = ri * 2 + ci;          // 0=P 1=Q 2=R 3=S
                    int r = rr[ri], c = cc[ci];
                    float Am = 0.f;
                    unsigned g = 0u;
                    if (r < HH && c < EE) {
                        int uu2 = r + (c >> 1) - ADDC;
                        if (uu2 >= 0 && uu2 < EE) {
                            if (obst[(b * EE + uu2) * EE + c] == 0.0f) {
                                Am = GAMMA;
                                #pragma unroll
                                for (int j = 0; j < NJ; ++j)
                                    if (goals[((b * NJ + j) * EE + uu2) * EE + c] != 0.0f)
                                        g |= (1u << j);
                            }
                        }
                    }
                    Amv[cell] = Am;
                    int shift = cell * 6;
                    cgq[u] |= g << shift;
                }
            }
            AmP[u] = Amv[0]; AmQ[u] = Amv[1]; AmR[u] = Amv[2]; AmS[u] = Amv[3];

            oP0[u] = make_float2(bf(cgq[u], 0),  bf(cgq[u], 3));
            oP1[u] = make_float2(bf(cgq[u], 1),  bf(cgq[u], 4));
            oP2[u] = make_float2(bf(cgq[u], 2),  bf(cgq[u], 5));
            oQ0[u] = make_float2(bf(cgq[u], 6),  bf(cgq[u], 9));
            oQ1[u] = make_float2(bf(cgq[u], 7),  bf(cgq[u], 10));
            oQ2[u] = make_float2(bf(cgq[u], 8),  bf(cgq[u], 11));
            oR0[u] = make_float2(bf(cgq[u], 12), bf(cgq[u], 15));
            oR1[u] = make_float2(bf(cgq[u], 13), bf(cgq[u], 16));
            oR2[u] = make_float2(bf(cgq[u], 14), bf(cgq[u], 17));
            oS0[u] = make_float2(bf(cgq[u], 18), bf(cgq[u], 21));
            oS1[u] = make_float2(bf(cgq[u], 19), bf(cgq[u], 22));
            oS2[u] = make_float2(bf(cgq[u], 20), bf(cgq[u], 23));

            float2* Db = smf2;   // buffer A
            *(float4*)(Db + k0[u])      = make_float4(oP0[u].x, oP0[u].y, oQ0[u].x, oQ0[u].y);
            *(float4*)(Db + k0[u] + 30) = make_float4(oR0[u].x, oR0[u].y, oS0[u].x, oS0[u].y);
            *(float4*)(Db + k1[u])      = make_float4(oP1[u].x, oP1[u].y, oQ1[u].x, oQ1[u].y);
            *(float4*)(Db + k1[u] + 30) = make_float4(oR1[u].x, oR1[u].y, oS1[u].x, oS1[u].y);
            *(float4*)(Db + k2[u])      = make_float4(oP2[u].x, oP2[u].y, oQ2[u].x, oQ2[u].y);
            *(float4*)(Db + k2[u] + 30) = make_float4(oR2[u].x, oR2[u].y, oS2[u].x, oS2[u].y);
        }
    }
    __syncthreads();

    const int iters = n_iter[0];
    int spO2 = 0;

    for (int s = 0; s < iters; ++s) {
        const float2* Sb = smf2 + spO2;
        float2*       Db = smf2 + (spO2 ^ NF2);

        #pragma unroll
        for (int u = 0; u < NU; ++u) {
            if (act[u]) {
                // 12 loads (10 neighbors come from registers)
                float2 A  = Sb[k0[u] - 1];
                float2 Bx = Sb[k0[u] + 29];
                float2 C  = Sb[k0[u] + 2];
                float2 D  = Sb[k0[u] + 32];
                float4 U4 = *(const float4*)(Sb + (k1[u] - 30));
                float4 N4 = *(const float4*)(Sb + (k1[u] + 60));
                float2 E  = Sb[k2[u] + 29];
                float2 F  = Sb[k2[u] + 59];
                float2 G  = Sb[k2[u] + 60];
                float2 Hh = Sb[k2[u] - 29];
                float2 I  = Sb[k2[u] - 28];
                float2 J  = Sb[k2[u] + 2];

                // P: n0=oQ0 n1=oR1 n2=E n3=A n4=U.lo n5=Hh
                float mP0 = fmaxf(fmaxf(oQ0[u].x, A.x),  fmaxf(oP1[u].x, oP2[u].y));
                float mP1 = fmaxf(fmaxf(oR1[u].x, U4.x), fmaxf(oP2[u].x, oP0[u].x));
                float mP2 = fmaxf(fmaxf(E.x,   Hh.x), fmaxf(oP0[u].y, oP1[u].x));
                float mP3 = fmaxf(fmaxf(A.y,   oQ0[u].y), fmaxf(oP1[u].y, oP2[u].x));
                float mP4 = fmaxf(fmaxf(U4.y,  oR1[u].y), fmaxf(oP2[u].y, oP0[u].y));
                float mP5 = fmaxf(fmaxf(Hh.y,  E.y),  fmaxf(oP0[u].x, oP1[u].y));

                // Q: n0=C n1=oS1 n2=oR2 n3=oP0 n4=U.hi n5=I
                float mQ0 = fmaxf(fmaxf(C.x,   oP0[u].x), fmaxf(oQ1[u].x, oQ2[u].y));
                float mQ1 = fmaxf(fmaxf(oS1[u].x, U4.z), fmaxf(oQ2[u].x, oQ0[u].x));
                float mQ2 = fmaxf(fmaxf(oR2[u].x, I.x),  fmaxf(oQ0[u].y, oQ1[u].x));
                float mQ3 = fmaxf(fmaxf(oP0[u].y, C.y),  fmaxf(oQ1[u].y, oQ2[u].x));
                float mQ4 = fmaxf(fmaxf(U4.w,  oS1[u].y), fmaxf(oQ2[u].y, oQ0[u].y));
                float mQ5 = fmaxf(fmaxf(I.y,   oR2[u].y), fmaxf(oQ0[u].x, oQ1[u].y));

                // R: n0=oS0 n1=N.lo n2=F n3=Bx n4=oP1 n5=oQ2
                float mR0 = fmaxf(fmaxf(oS0[u].x, Bx.x), fmaxf(oR1[u].x, oR2[u].y));
                float mR1 = fmaxf(fmaxf(N4.x,  oP1[u].x), fmaxf(oR2[u].x, oR0[u].x));
                float mR2 = fmaxf(fmaxf(F.x,   oQ2[u].x), fmaxf(oR0[u].y, oR1[u].x));
                float mR3 = fmaxf(fmaxf(Bx.y,  oS0[u].y), fmaxf(oR1[u].y, oR2[u].x));
                float mR4 = fmaxf(fmaxf(oP1[u].y, N4.y), fmaxf(oR2[u].y, oR0[u].y));
                float mR5 = fmaxf(fmaxf(oQ2[u].y, F.y),  fmaxf(oR0[u].x, oR1[u].y));

                // S: n0=D n1=N.hi n2=G n3=oR0 n4=oQ1 n5=J
                float mS0 = fmaxf(fmaxf(D.x,   oR0[u].x), fmaxf(oS1[u].x, oS2[u].y));
                float mS1 = fmaxf(fmaxf(N4.z,  oQ1[u].x), fmaxf(oS2[u].x, oS0[u].x));
                float mS2 = fmaxf(fmaxf(G.x,   J.x),  fmaxf(oS0[u].y, oS1[u].x));
                float mS3 = fmaxf(fmaxf(oR0[u].y, D.y),  fmaxf(oS1[u].y, oS2[u].x));
                float mS4 = fmaxf(fmaxf(oQ1[u].y, N4.w), fmaxf(oS2[u].y, oS0[u].y));
                float mS5 = fmaxf(fmaxf(J.y,   G.y),  fmaxf(oS0[u].x, oS1[u].y));

                oP0[u].x = fmaf(AmP[u], mP0, bf(cgq[u], 0));
                oP0[u].y = fmaf(AmP[u], mP3, bf(cgq[u], 3));
                oP1[u].x = fmaf(AmP[u], mP1, bf(cgq[u], 1));
                oP1[u].y = fmaf(AmP[u], mP4, bf(cgq[u], 4));
                oP2[u].x = fmaf(AmP[u], mP2, bf(cgq[u], 2));
                oP2[u].y = fmaf(AmP[u], mP5, bf(cgq[u], 5));
                oQ0[u].x = fmaf(AmQ[u], mQ0, bf(cgq[u], 6));
                oQ0[u].y = fmaf(AmQ[u], mQ3, bf(cgq[u], 9));
                oQ1[u].x = fmaf(AmQ[u], mQ1, bf(cgq[u], 7));
                oQ1[u].y = fmaf(AmQ[u], mQ4, bf(cgq[u], 10));
                oQ2[u].x = fmaf(AmQ[u], mQ2, bf(cgq[u], 8));
                oQ2[u].y = fmaf(AmQ[u], mQ5, bf(cgq[u], 11));
                oR0[u].x = fmaf(AmR[u], mR0, bf(cgq[u], 12));
                oR0[u].y = fmaf(AmR[u], mR3, bf(cgq[u], 15));
                oR1[u].x = fmaf(AmR[u], mR1, bf(cgq[u], 13));
                oR1[u].y = fmaf(AmR[u], mR4, bf(cgq[u], 16));
                oR2[u].x = fmaf(AmR[u], mR2, bf(cgq[u], 14));
                oR2[u].y = fmaf(AmR[u], mR5, bf(cgq[u], 17));
                oS0[u].x = fmaf(AmS[u], mS0, bf(cgq[u], 18));
                oS0[u].y = fmaf(AmS[u], mS3, bf(cgq[u], 21));
                oS1[u].x = fmaf(AmS[u], mS1, bf(cgq[u], 19));
                oS1[u].y = fmaf(AmS[u], mS4, bf(cgq[u], 22));
                oS2[u].x = fmaf(AmS[u], mS2, bf(cgq[u], 20));
                oS2[u].y = fmaf(AmS[u], mS5, bf(cgq[u], 23));

                *(float4*)(Db + k0[u])      = make_float4(oP0[u].x, oP0[u].y, oQ0[u].x, oQ0[u].y);
                *(float4*)(Db + k0[u] + 30) = make_float4(oR0[u].x, oR0[u].y, oS0[u].x, oS0[u].y);
                *(float4*)(Db + k1[u])      = make_float4(oP1[u].x, oP1[u].y, oQ1[u].x, oQ1[u].y);
                *(float4*)(Db + k1[u] + 30) = make_float4(oR1[u].x, oR1[u].y, oS1[u].x, oS1[u].y);
                *(float4*)(Db + k2[u])      = make_float4(oP2[u].x, oP2[u].y, oQ2[u].x, oQ2[u].y);
                *(float4*)(Db + k2[u] + 30) = make_float4(oR2[u].x, oR2[u].y, oS2[u].x, oS2[u].y);
            }
        }
        spO2 ^= NF2;
        __syncthreads();
    }
    // final s_plus in buffer at offset spO2

    if (tid < 4) {
        int a     = tid;
        int alpha = state[b * 3 + 0];
        int u     = state[b * 3 + 1];
        int v     = state[b * 3 + 2];
        int rot   = (alpha + 1) % 6;
        int uu    = u - (v >> 1) + ADDC;

        int p, ddr = 0, ddc = 0;
        int drr = (int)((DR_PACK >> (2 * rot)) & 3u) - 1;
        int dcc = (int)((DC_PACK >> (2 * rot)) & 3u) - 1;
        if (a == 0)      { p = rot; ddr =  drr; ddc =  dcc; }
        else if (a == 1) { p = rot; ddr = -drr; ddc = -dcc; }
        else if (a == 2) { p = (rot + 1) % 6; }
        else             { p = (rot + 5) % 6; }

        float qv = 0.0f;
        if (obst[(b * EE + u) * EE + v] == 0.0f) {
            int pm   = p % 3;
            int base = (pm == 0) ? P0B : ((pm == 1) ? P1B : P2B);
            int prow = (pm == 0) ? uu : (uu + ddr + 1);
            float2 val = smf2[spO2 + base + prow * PEC + (v + ddc + 2)];
            qv = (p < 3) ? val.x : val.y;
        }
        out[b * 4 + a] = qv;
    }
}

extern "C" void kernel_launch(void* const* d_in, const int* in_sizes, int n_in,
                              void* d_out, int out_size) {
    const float* goals  = (const float*)d_in[0];
    const int*   state  = (const int*)  d_in[1];
    const float* obst   = (const float*)d_in[2];
    const int*   n_iter = (const int*)  d_in[3];
    float* out = (float*)d_out;

    cudaFuncSetAttribute(vin_kernel,
                         cudaFuncAttributeMaxDynamicSharedMemorySize, SMEM_BYTES);

    int B = out_size / 4;   // 512
    vin_kernel<<<B, NTH, SMEM_BYTES>>>(goals, state, obst, n_iter, out);
}